// round 2
// baseline (speedup 1.0000x reference)
#include <cuda_runtime.h>
#include <math.h>

#define BB 4
#define LL 2048
#define DD 512
#define NROW (BB*LL)

typedef unsigned long long u64;

// ---- packed fp32x2 helpers (sm_100a): full-rate fp32 FMA path ----
__device__ __forceinline__ u64 pk2(float x, float y) {
    u64 r; asm("mov.b64 %0, {%1, %2};" : "=l"(r) : "f"(x), "f"(y)); return r;
}
__device__ __forceinline__ void upk2(u64 v, float& x, float& y) {
    asm("mov.b64 {%0, %1}, %2;" : "=f"(x), "=f"(y) : "l"(v));
}
__device__ __forceinline__ u64 ffma2(u64 a, u64 b, u64 c) {
    u64 d; asm("fma.rn.f32x2 %0, %1, %2, %3;" : "=l"(d) : "l"(a), "l"(b), "l"(c)); return d;
}
__device__ __forceinline__ u64 fmul2(u64 a, u64 b) {
    u64 d; asm("mul.rn.f32x2 %0, %1, %2;" : "=l"(d) : "l"(a), "l"(b)); return d;
}

// ---- scratch (static device memory; no allocations anywhere) ----
__device__ float g_xact[NROW*DD];   // tanh(x)          16 MB
__device__ float g_stat[NROW*DD];   // x_act @ W^T      16 MB
__device__ float g_odyn[NROW*DD];   // scan output      16 MB
__device__ float g_kk[NROW];        // per-row k.k

// ============================================================
// 1) prep: x_act = tanh(x), kk[row] = sum(x_act^2)
// ============================================================
__global__ void prep_kernel(const float* __restrict__ x) {
    int row = blockIdx.x;
    int t = threadIdx.x;
    const float4* xin = reinterpret_cast<const float4*>(x + (size_t)row * DD);
    float4* xo = reinterpret_cast<float4*>(g_xact + (size_t)row * DD);
    float4 v = xin[t];
    float4 a;
    a.x = tanhf(v.x); a.y = tanhf(v.y); a.z = tanhf(v.z); a.w = tanhf(v.w);
    xo[t] = a;
    float ss = a.x*a.x + a.y*a.y + a.z*a.z + a.w*a.w;
    __shared__ float red[4];
    #pragma unroll
    for (int o = 16; o > 0; o >>= 1) ss += __shfl_xor_sync(0xffffffffu, ss, o);
    if ((t & 31) == 0) red[t >> 5] = ss;
    __syncthreads();
    if (t == 0) g_kk[row] = red[0] + red[1] + red[2] + red[3];
}

// ============================================================
// 2) SGEMM (f32x2): g_stat[m,n] = sum_d g_xact[m,d] * W[n,d]
//    128x128 tile, BK=8, 256 threads, 8x8 microtile packed
//    as 8x4 f32x2 accumulators (pairs along N).
// ============================================================
#define BM 128
#define BN 128
#define BK 8

__global__ __launch_bounds__(256) void gemm_kernel(const float* __restrict__ W) {
    __shared__ __align__(16) float As[BK][BM];
    __shared__ __align__(16) float Bs[BK][BN];
    int tid = threadIdx.x;
    int bn = blockIdx.x;   // 0..3
    int bm = blockIdx.y;   // 0..63

    int lr = tid >> 1;            // 0..127 (row within tile)
    int lc = (tid & 1) * 4;       // 0 or 4 (k offset, float4)
    const float* Ag = g_xact + ((size_t)bm * BM + lr) * DD + lc;
    const float* Bg = W      + ((size_t)bn * BN + lr) * DD + lc;

    int tx = tid & 15, ty = tid >> 4;
    int r0 = ty * 8, c0 = tx * 8;

    // acc2[i][jp]: row r0+i, column pair (c0+2jp, c0+2jp+1)
    u64 acc2[8][4];
    #pragma unroll
    for (int i = 0; i < 8; i++)
        #pragma unroll
        for (int j = 0; j < 4; j++) acc2[i][j] = 0ull;

    for (int k0 = 0; k0 < DD; k0 += BK) {
        float4 av = *reinterpret_cast<const float4*>(Ag + k0);
        float4 bv = *reinterpret_cast<const float4*>(Bg + k0);
        As[lc + 0][lr] = av.x; As[lc + 1][lr] = av.y;
        As[lc + 2][lr] = av.z; As[lc + 3][lr] = av.w;
        Bs[lc + 0][lr] = bv.x; Bs[lc + 1][lr] = bv.y;
        Bs[lc + 2][lr] = bv.z; Bs[lc + 3][lr] = bv.w;
        __syncthreads();
        #pragma unroll
        for (int k = 0; k < BK; k++) {
            float4 a0 = *reinterpret_cast<const float4*>(&As[k][r0]);
            float4 a1 = *reinterpret_cast<const float4*>(&As[k][r0 + 4]);
            // B pairs come free: contiguous floats reinterpreted as f32x2
            ulonglong2 bv0 = *reinterpret_cast<const ulonglong2*>(&Bs[k][c0]);
            ulonglong2 bv1 = *reinterpret_cast<const ulonglong2*>(&Bs[k][c0 + 4]);
            u64 bp[4] = {bv0.x, bv0.y, bv1.x, bv1.y};
            u64 ap[8];
            ap[0] = pk2(a0.x, a0.x); ap[1] = pk2(a0.y, a0.y);
            ap[2] = pk2(a0.z, a0.z); ap[3] = pk2(a0.w, a0.w);
            ap[4] = pk2(a1.x, a1.x); ap[5] = pk2(a1.y, a1.y);
            ap[6] = pk2(a1.z, a1.z); ap[7] = pk2(a1.w, a1.w);
            #pragma unroll
            for (int i = 0; i < 8; i++)
                #pragma unroll
                for (int j = 0; j < 4; j++)
                    acc2[i][j] = ffma2(ap[i], bp[j], acc2[i][j]);
        }
        __syncthreads();
    }

    #pragma unroll
    for (int i = 0; i < 8; i++) {
        float* cp = g_stat + ((size_t)bm * BM + r0 + i) * DD + bn * BN + c0;
        ulonglong2 w0, w1;
        w0.x = acc2[i][0]; w0.y = acc2[i][1];
        w1.x = acc2[i][2]; w1.y = acc2[i][3];
        *reinterpret_cast<ulonglong2*>(cp)     = w0;
        *reinterpret_cast<ulonglong2*>(cp + 4) = w1;
    }
}

// ============================================================
// 3) scan (f32x2, 2-step pipelined): gated delta rule, column-sharded.
//    Each 16-lane group owns one v-column of S (512 floats = 16 f32x2/lane).
//    Chunk-rescaled state S' = S / lam^t (rescale by lam^64 every 64 steps).
// ============================================================
__global__ __launch_bounds__(128) void scan_kernel(const float* __restrict__ eta_p,
                                                   const float* __restrict__ laml_p) {
    float beta = eta_p[0];
    float lam = 1.0f / (1.0f + expf(-laml_p[0]));
    float invlam = 1.0f / lam;
    float lam64 = lam;
    #pragma unroll
    for (int i = 0; i < 6; i++) lam64 *= lam64;   // lam^64 by squaring
    u64 lam64p = pk2(lam64, lam64);

    int b    = blockIdx.y;
    int warp = threadIdx.x >> 5;
    int lane = threadIdx.x & 31;
    int g    = lane >> 4;         // half-warp group
    int s    = lane & 15;         // lane within group
    int col  = (blockIdx.x << 3) + (warp << 1) + g;   // 0..511

    const float* xb = g_xact + (size_t)b * LL * DD;
    const float* vb = g_stat + (size_t)b * LL * DD + col;
    const float* kb = g_kk   + (size_t)b * LL;
    float*       ob = g_odyn + (size_t)b * LL * DD + col;

    // state: S2[2j+h] = rows 4*(s+16j) + {2h, 2h+1}
    u64 S2[16];
    #pragma unroll
    for (int i = 0; i < 16; i++) S2[i] = 0ull;

    ulonglong2 KA[8], KB[8];
    {
        const ulonglong2* kp = reinterpret_cast<const ulonglong2*>(xb);
        #pragma unroll
        for (int j = 0; j < 8; j++) KA[j] = kp[s + 16 * j];
    }
    float vA = vb[0], kkA = kb[0];
    float vB, kkB;

    float p = lam, pinv = invlam;

#define SCAN_STEP(KC, VV, KK, TT) do {                                        \
        u64 a0 = 0ull, a1 = 0ull, a2 = 0ull, a3 = 0ull;                       \
        _Pragma("unroll")                                                     \
        for (int j = 0; j < 4; j++) {                                         \
            a0 = ffma2(KC[j].x, S2[2*j],   a0);                               \
            a1 = ffma2(KC[j].y, S2[2*j+1], a1);                               \
        }                                                                     \
        _Pragma("unroll")                                                     \
        for (int j = 4; j < 8; j++) {                                         \
            a2 = ffma2(KC[j].x, S2[2*j],   a2);                               \
            a3 = ffma2(KC[j].y, S2[2*j+1], a3);                               \
        }                                                                     \
        float x0,x1,x2,x3,x4,x5,x6,x7;                                        \
        upk2(a0,x0,x1); upk2(a1,x2,x3); upk2(a2,x4,x5); upk2(a3,x6,x7);       \
        float d = ((x0+x1)+(x2+x3)) + ((x4+x5)+(x6+x7));                      \
        d += __shfl_xor_sync(0xffffffffu, d, 1);                              \
        d += __shfl_xor_sync(0xffffffffu, d, 2);                              \
        d += __shfl_xor_sync(0xffffffffu, d, 4);                              \
        d += __shfl_xor_sync(0xffffffffu, d, 8);                              \
        float pd   = p * d;                                                   \
        float verr = beta * ((VV) - pd);                                      \
        float o    = pd + (KK) * verr;                                        \
        if (s == 0) ob[(size_t)(TT) * DD] = o;                                \
        float wv = pinv * verr;                                               \
        u64 w2 = pk2(wv, wv);                                                 \
        _Pragma("unroll")                                                     \
        for (int j = 0; j < 8; j++) {                                         \
            S2[2*j]   = ffma2(KC[j].x, w2, S2[2*j]);                          \
            S2[2*j+1] = ffma2(KC[j].y, w2, S2[2*j+1]);                        \
        }                                                                     \
    } while (0)

    for (int t = 0; t < LL; t += 2) {
        // prefetch t+1 into B buffers
        {
            const ulonglong2* kp = reinterpret_cast<const ulonglong2*>(xb + (size_t)(t + 1) * DD);
            #pragma unroll
            for (int j = 0; j < 8; j++) KB[j] = kp[s + 16 * j];
            vB  = vb[(size_t)(t + 1) * DD];
            kkB = kb[t + 1];
        }

        SCAN_STEP(KA, vA, kkA, t);
        // t even -> never a chunk boundary (boundaries at t%64==63, odd)
        p *= lam; pinv *= invlam;

        // prefetch t+2 into A buffers
        {
            int tn = (t + 2 < LL) ? (t + 2) : t;
            const ulonglong2* kp = reinterpret_cast<const ulonglong2*>(xb + (size_t)tn * DD);
            #pragma unroll
            for (int j = 0; j < 8; j++) KA[j] = kp[s + 16 * j];
            vA  = vb[(size_t)tn * DD];
            kkA = kb[tn];
        }

        SCAN_STEP(KB, vB, kkB, t + 1);
        if ((t & 63) == 62) {
            // chunk boundary at t+1: S <- lam^64 * S', reset powers
            #pragma unroll
            for (int i = 0; i < 16; i++) S2[i] = fmul2(S2[i], lam64p);
            p = lam; pinv = invlam;
        } else {
            p *= lam; pinv *= invlam;
        }
    }
#undef SCAN_STEP
}

// ============================================================
// 4) LayerNorm: y = stat + odyn; normalize over D; gamma/beta
// ============================================================
__global__ void ln_kernel(const float* __restrict__ gamma,
                          const float* __restrict__ lbeta,
                          float* __restrict__ out) {
    int row = blockIdx.x;
    int t = threadIdx.x;
    const float4* sp = reinterpret_cast<const float4*>(g_stat + (size_t)row * DD);
    const float4* op = reinterpret_cast<const float4*>(g_odyn + (size_t)row * DD);
    float4 sv = sp[t], ov = op[t];
    float4 y;
    y.x = sv.x + ov.x; y.y = sv.y + ov.y; y.z = sv.z + ov.z; y.w = sv.w + ov.w;

    float sum = y.x + y.y + y.z + y.w;
    float sq  = y.x*y.x + y.y*y.y + y.z*y.z + y.w*y.w;

    __shared__ float r1[4], r2[4];
    #pragma unroll
    for (int o = 16; o > 0; o >>= 1) {
        sum += __shfl_xor_sync(0xffffffffu, sum, o);
        sq  += __shfl_xor_sync(0xffffffffu, sq, o);
    }
    if ((t & 31) == 0) { r1[t >> 5] = sum; r2[t >> 5] = sq; }
    __syncthreads();
    __shared__ float smu, srs;
    if (t == 0) {
        float ts = r1[0] + r1[1] + r1[2] + r1[3];
        float tq = r2[0] + r2[1] + r2[2] + r2[3];
        float mu = ts * (1.0f / DD);
        float var = tq * (1.0f / DD) - mu * mu;
        smu = mu;
        srs = rsqrtf(var + 1e-5f);
    }
    __syncthreads();
    float mu = smu, rs = srs;

    const float4* gp = reinterpret_cast<const float4*>(gamma);
    const float4* bp = reinterpret_cast<const float4*>(lbeta);
    float4 gv = gp[t], bv = bp[t];
    float4 r;
    r.x = (y.x - mu) * rs * gv.x + bv.x;
    r.y = (y.y - mu) * rs * gv.y + bv.y;
    r.z = (y.z - mu) * rs * gv.z + bv.z;
    r.w = (y.w - mu) * rs * gv.w + bv.w;
    reinterpret_cast<float4*>(out + (size_t)row * DD)[t] = r;
}

// ============================================================
extern "C" void kernel_launch(void* const* d_in, const int* in_sizes, int n_in,
                              void* d_out, int out_size) {
    const float* x     = (const float*)d_in[0];
    const float* W     = (const float*)d_in[1];
    const float* eta   = (const float*)d_in[2];
    const float* laml  = (const float*)d_in[3];
    const float* gamma = (const float*)d_in[4];
    const float* lbeta = (const float*)d_in[5];
    float* out = (float*)d_out;

    prep_kernel<<<NROW, 128>>>(x);
    gemm_kernel<<<dim3(DD / BN, NROW / BM), 256>>>(W);
    scan_kernel<<<dim3(DD / 8, BB), 128>>>(eta, laml);
    ln_kernel<<<NROW, 128>>>(gamma, lbeta, out);
}

// round 3
// speedup vs baseline: 1.0063x; 1.0063x over previous
#include <cuda_runtime.h>
#include <math.h>

#define BB 4
#define LL 2048
#define DD 512
#define NROW (BB*LL)

typedef unsigned long long u64;

// ---- packed fp32x2 helpers ----
__device__ __forceinline__ u64 pk2(float x, float y) {
    u64 r; asm("mov.b64 %0, {%1, %2};" : "=l"(r) : "f"(x), "f"(y)); return r;
}
__device__ __forceinline__ void upk2(u64 v, float& x, float& y) {
    asm("mov.b64 {%0, %1}, %2;" : "=f"(x), "=f"(y) : "l"(v));
}
__device__ __forceinline__ u64 ffma2(u64 a, u64 b, u64 c) {
    u64 d; asm("fma.rn.f32x2 %0, %1, %2, %3;" : "=l"(d) : "l"(a), "l"(b), "l"(c)); return d;
}
__device__ __forceinline__ u64 fmul2(u64 a, u64 b) {
    u64 d; asm("mul.rn.f32x2 %0, %1, %2;" : "=l"(d) : "l"(a), "l"(b)); return d;
}

// ---- scratch ----
__device__ float g_xact[NROW*DD];
__device__ float g_stat[NROW*DD];
__device__ float g_odyn[NROW*DD];
__device__ float g_kk[NROW];

// ============================================================
// 1) prep
// ============================================================
__global__ void prep_kernel(const float* __restrict__ x) {
    int row = blockIdx.x;
    int t = threadIdx.x;
    const float4* xin = reinterpret_cast<const float4*>(x + (size_t)row * DD);
    float4* xo = reinterpret_cast<float4*>(g_xact + (size_t)row * DD);
    float4 v = xin[t];
    float4 a;
    a.x = tanhf(v.x); a.y = tanhf(v.y); a.z = tanhf(v.z); a.w = tanhf(v.w);
    xo[t] = a;
    float ss = a.x*a.x + a.y*a.y + a.z*a.z + a.w*a.w;
    __shared__ float red[4];
    #pragma unroll
    for (int o = 16; o > 0; o >>= 1) ss += __shfl_xor_sync(0xffffffffu, ss, o);
    if ((t & 31) == 0) red[t >> 5] = ss;
    __syncthreads();
    if (t == 0) g_kk[row] = red[0] + red[1] + red[2] + red[3];
}

// ============================================================
// 2) SGEMM, A pre-packed to (a,a) pairs in SMEM
// ============================================================
#define BM 128
#define BN 128
#define BK 8

__global__ __launch_bounds__(256) void gemm_kernel(const float* __restrict__ W) {
    __shared__ __align__(16) u64   As2[BK][BM];   // (a,a) pairs, 8KB
    __shared__ __align__(16) float Bs[BK][BN];    // 4KB
    int tid = threadIdx.x;
    int bn = blockIdx.x;
    int bm = blockIdx.y;

    int lr = tid >> 1;
    int lc = (tid & 1) * 4;
    const float* Ag = g_xact + ((size_t)bm * BM + lr) * DD + lc;
    const float* Bg = W      + ((size_t)bn * BN + lr) * DD + lc;

    int tx = tid & 15, ty = tid >> 4;
    int r0 = ty * 8, c0 = tx * 8;

    u64 acc2[8][4];
    #pragma unroll
    for (int i = 0; i < 8; i++)
        #pragma unroll
        for (int j = 0; j < 4; j++) acc2[i][j] = 0ull;

    for (int k0 = 0; k0 < DD; k0 += BK) {
        float4 av = *reinterpret_cast<const float4*>(Ag + k0);
        float4 bv = *reinterpret_cast<const float4*>(Bg + k0);
        As2[lc + 0][lr] = pk2(av.x, av.x);
        As2[lc + 1][lr] = pk2(av.y, av.y);
        As2[lc + 2][lr] = pk2(av.z, av.z);
        As2[lc + 3][lr] = pk2(av.w, av.w);
        Bs[lc + 0][lr] = bv.x; Bs[lc + 1][lr] = bv.y;
        Bs[lc + 2][lr] = bv.z; Bs[lc + 3][lr] = bv.w;
        __syncthreads();
        #pragma unroll
        for (int k = 0; k < BK; k++) {
            ulonglong2 aa0 = *reinterpret_cast<const ulonglong2*>(&As2[k][r0]);
            ulonglong2 aa1 = *reinterpret_cast<const ulonglong2*>(&As2[k][r0 + 2]);
            ulonglong2 aa2 = *reinterpret_cast<const ulonglong2*>(&As2[k][r0 + 4]);
            ulonglong2 aa3 = *reinterpret_cast<const ulonglong2*>(&As2[k][r0 + 6]);
            ulonglong2 bv0 = *reinterpret_cast<const ulonglong2*>(&Bs[k][c0]);
            ulonglong2 bv1 = *reinterpret_cast<const ulonglong2*>(&Bs[k][c0 + 4]);
            u64 ap[8] = {aa0.x, aa0.y, aa1.x, aa1.y, aa2.x, aa2.y, aa3.x, aa3.y};
            u64 bp[4] = {bv0.x, bv0.y, bv1.x, bv1.y};
            #pragma unroll
            for (int i = 0; i < 8; i++)
                #pragma unroll
                for (int j = 0; j < 4; j++)
                    acc2[i][j] = ffma2(ap[i], bp[j], acc2[i][j]);
        }
        __syncthreads();
    }

    #pragma unroll
    for (int i = 0; i < 8; i++) {
        float* cp = g_stat + ((size_t)bm * BM + r0 + i) * DD + bn * BN + c0;
        ulonglong2 w0, w1;
        w0.x = acc2[i][0]; w0.y = acc2[i][1];
        w1.x = acc2[i][2]; w1.y = acc2[i][3];
        *reinterpret_cast<ulonglong2*>(cp)     = w0;
        *reinterpret_cast<ulonglong2*>(cp + 4) = w1;
    }
}

// ============================================================
// 3) scan: one WARP per 2 adjacent columns.
//    Lane owns row pairs row = 64p + 2*lane + {0,1}, p = 0..7.
//    k loaded as 8 coalesced LDG.64 per warp per step (2KB min traffic).
//    Chunk-rescaled state S' = S / lam^t (rescale by lam^64 / 64 steps).
//    128 blocks x 256 thr = 1024 warps = one wave.
// ============================================================
__global__ __launch_bounds__(256) void scan_kernel(const float* __restrict__ eta_p,
                                                   const float* __restrict__ laml_p) {
    float beta = eta_p[0];
    float lam = 1.0f / (1.0f + expf(-laml_p[0]));
    float invlam = 1.0f / lam;
    float lam64 = lam;
    #pragma unroll
    for (int i = 0; i < 6; i++) lam64 *= lam64;
    u64 lam64p = pk2(lam64, lam64);

    int wid  = threadIdx.x >> 5;
    int lane = threadIdx.x & 31;
    int b    = blockIdx.x >> 5;                         // 32 blocks per batch
    int cp   = ((blockIdx.x & 31) << 3) + wid;          // column pair 0..255
    int col  = cp << 1;

    const float* xb = g_xact + (size_t)b * LL * DD + 2 * lane;  // lane's k base
    const float* vb = g_stat + (size_t)b * LL * DD + col;
    const float* kb = g_kk   + (size_t)b * LL;
    float*       ob = g_odyn + (size_t)b * LL * DD + col;

    // S2[2p + c]: rows (64p + 2*lane, +1) of column col+c
    u64 S2[16];
    #pragma unroll
    for (int i = 0; i < 16; i++) S2[i] = 0ull;

    u64 KA[8], KB[8];
    #pragma unroll
    for (int p = 0; p < 8; p++)
        KA[p] = *reinterpret_cast<const u64*>(xb + 64 * p);
    float2 vA = *reinterpret_cast<const float2*>(vb);
    float  kkA = kb[0];
    float2 vB; float kkB;

    float p = lam, pinv = invlam;

#define SCAN_STEP(KC, VV, KK, TT) do {                                        \
        u64 a0a = 0ull, a0b = 0ull, a1a = 0ull, a1b = 0ull;                   \
        _Pragma("unroll")                                                     \
        for (int q = 0; q < 4; q++) {                                         \
            a0a = ffma2(KC[q], S2[2*q],   a0a);                               \
            a1a = ffma2(KC[q], S2[2*q+1], a1a);                               \
        }                                                                     \
        _Pragma("unroll")                                                     \
        for (int q = 4; q < 8; q++) {                                         \
            a0b = ffma2(KC[q], S2[2*q],   a0b);                               \
            a1b = ffma2(KC[q], S2[2*q+1], a1b);                               \
        }                                                                     \
        float y0, y1, y2, y3, z0, z1, z2, z3;                                 \
        upk2(a0a, y0, y1); upk2(a0b, y2, y3);                                 \
        upk2(a1a, z0, z1); upk2(a1b, z2, z3);                                 \
        float d0 = (y0 + y1) + (y2 + y3);                                     \
        float d1 = (z0 + z1) + (z2 + z3);                                     \
        _Pragma("unroll")                                                     \
        for (int o = 1; o < 32; o <<= 1) {                                    \
            d0 += __shfl_xor_sync(0xffffffffu, d0, o);                        \
            d1 += __shfl_xor_sync(0xffffffffu, d1, o);                        \
        }                                                                     \
        float pd0 = p * d0,  pd1 = p * d1;                                    \
        float ve0 = beta * ((VV).x - pd0);                                    \
        float ve1 = beta * ((VV).y - pd1);                                    \
        if (lane == 0) {                                                      \
            float2 oo; oo.x = pd0 + (KK) * ve0; oo.y = pd1 + (KK) * ve1;      \
            *reinterpret_cast<float2*>(ob + (size_t)(TT) * DD) = oo;          \
        }                                                                     \
        u64 w0 = pk2(pinv * ve0, pinv * ve0);                                 \
        u64 w1 = pk2(pinv * ve1, pinv * ve1);                                 \
        _Pragma("unroll")                                                     \
        for (int q = 0; q < 8; q++) {                                         \
            S2[2*q]   = ffma2(KC[q], w0, S2[2*q]);                            \
            S2[2*q+1] = ffma2(KC[q], w1, S2[2*q+1]);                          \
        }                                                                     \
    } while (0)

    for (int t = 0; t < LL; t += 2) {
        // prefetch t+1 -> B
        {
            const float* kp = xb + (size_t)(t + 1) * DD;
            #pragma unroll
            for (int q = 0; q < 8; q++)
                KB[q] = *reinterpret_cast<const u64*>(kp + 64 * q);
            vB  = *reinterpret_cast<const float2*>(vb + (size_t)(t + 1) * DD);
            kkB = kb[t + 1];
        }

        SCAN_STEP(KA, vA, kkA, t);
        p *= lam; pinv *= invlam;        // t even: never a chunk boundary

        // prefetch t+2 -> A
        {
            int tn = (t + 2 < LL) ? (t + 2) : t;
            const float* kp = xb + (size_t)tn * DD;
            #pragma unroll
            for (int q = 0; q < 8; q++)
                KA[q] = *reinterpret_cast<const u64*>(kp + 64 * q);
            vA  = *reinterpret_cast<const float2*>(vb + (size_t)tn * DD);
            kkA = kb[tn];
        }

        SCAN_STEP(KB, vB, kkB, t + 1);
        if ((t & 63) == 62) {
            #pragma unroll
            for (int i = 0; i < 16; i++) S2[i] = fmul2(S2[i], lam64p);
            p = lam; pinv = invlam;
        } else {
            p *= lam; pinv *= invlam;
        }
    }
#undef SCAN_STEP
}

// ============================================================
// 4) LayerNorm
// ============================================================
__global__ void ln_kernel(const float* __restrict__ gamma,
                          const float* __restrict__ lbeta,
                          float* __restrict__ out) {
    int row = blockIdx.x;
    int t = threadIdx.x;
    const float4* sp = reinterpret_cast<const float4*>(g_stat + (size_t)row * DD);
    const float4* op = reinterpret_cast<const float4*>(g_odyn + (size_t)row * DD);
    float4 sv = sp[t], ov = op[t];
    float4 y;
    y.x = sv.x + ov.x; y.y = sv.y + ov.y; y.z = sv.z + ov.z; y.w = sv.w + ov.w;

    float sum = y.x + y.y + y.z + y.w;
    float sq  = y.x*y.x + y.y*y.y + y.z*y.z + y.w*y.w;

    __shared__ float r1[4], r2[4];
    #pragma unroll
    for (int o = 16; o > 0; o >>= 1) {
        sum += __shfl_xor_sync(0xffffffffu, sum, o);
        sq  += __shfl_xor_sync(0xffffffffu, sq, o);
    }
    if ((t & 31) == 0) { r1[t >> 5] = sum; r2[t >> 5] = sq; }
    __syncthreads();
    __shared__ float smu, srs;
    if (t == 0) {
        float ts = r1[0] + r1[1] + r1[2] + r1[3];
        float tq = r2[0] + r2[1] + r2[2] + r2[3];
        float mu = ts * (1.0f / DD);
        float var = tq * (1.0f / DD) - mu * mu;
        smu = mu;
        srs = rsqrtf(var + 1e-5f);
    }
    __syncthreads();
    float mu = smu, rs = srs;

    const float4* gp = reinterpret_cast<const float4*>(gamma);
    const float4* bp = reinterpret_cast<const float4*>(lbeta);
    float4 gv = gp[t], bv = bp[t];
    float4 r;
    r.x = (y.x - mu) * rs * gv.x + bv.x;
    r.y = (y.y - mu) * rs * gv.y + bv.y;
    r.z = (y.z - mu) * rs * gv.z + bv.z;
    r.w = (y.w - mu) * rs * gv.w + bv.w;
    reinterpret_cast<float4*>(out + (size_t)row * DD)[t] = r;
}

// ============================================================
extern "C" void kernel_launch(void* const* d_in, const int* in_sizes, int n_in,
                              void* d_out, int out_size) {
    const float* x     = (const float*)d_in[0];
    const float* W     = (const float*)d_in[1];
    const float* eta   = (const float*)d_in[2];
    const float* laml  = (const float*)d_in[3];
    const float* gamma = (const float*)d_in[4];
    const float* lbeta = (const float*)d_in[5];
    float* out = (float*)d_out;

    prep_kernel<<<NROW, 128>>>(x);
    gemm_kernel<<<dim3(DD / BN, NROW / BM), 256>>>(W);
    scan_kernel<<<128, 256>>>(eta, laml);
    ln_kernel<<<NROW, 128>>>(gamma, lbeta, out);
}

// round 4
// speedup vs baseline: 1.0079x; 1.0016x over previous
#include <cuda_runtime.h>
#include <math.h>

#define BB 4
#define LL 2048
#define DD 512
#define NROW (BB*LL)

typedef unsigned long long u64;

// ---- packed fp32x2 helpers ----
__device__ __forceinline__ u64 pk2(float x, float y) {
    u64 r; asm("mov.b64 %0, {%1, %2};" : "=l"(r) : "f"(x), "f"(y)); return r;
}
__device__ __forceinline__ void upk2(u64 v, float& x, float& y) {
    asm("mov.b64 {%0, %1}, %2;" : "=f"(x), "=f"(y) : "l"(v));
}
__device__ __forceinline__ u64 ffma2(u64 a, u64 b, u64 c) {
    u64 d; asm("fma.rn.f32x2 %0, %1, %2, %3;" : "=l"(d) : "l"(a), "l"(b), "l"(c)); return d;
}
__device__ __forceinline__ u64 fmul2(u64 a, u64 b) {
    u64 d; asm("mul.rn.f32x2 %0, %1, %2;" : "=l"(d) : "l"(a), "l"(b)); return d;
}

// ---- fast tanh: branchless, ~1e-6 abs error, MUFU-based (no precise div) ----
__device__ __forceinline__ float fast_tanh(float x) {
    float ax = fabsf(x);
    float e  = __expf(2.0f * ax);            // ex2.approx path, always >= 1
    float t  = 1.0f - __fdividef(2.0f, e + 1.0f);  // rcp.approx + mul
    return copysignf(t, x);
}

// ---- scratch ----
__device__ float g_xact[NROW*DD];
__device__ float g_stat[NROW*DD];
__device__ float g_odyn[NROW*DD];
__device__ float g_kk[NROW];

// ============================================================
// 1) prep: x_act = tanh(x), kk[row] = sum(x_act^2)
// ============================================================
__global__ void prep_kernel(const float* __restrict__ x) {
    int row = blockIdx.x;
    int t = threadIdx.x;
    const float4* xin = reinterpret_cast<const float4*>(x + (size_t)row * DD);
    float4* xo = reinterpret_cast<float4*>(g_xact + (size_t)row * DD);
    float4 v = xin[t];
    float4 a;
    a.x = fast_tanh(v.x); a.y = fast_tanh(v.y);
    a.z = fast_tanh(v.z); a.w = fast_tanh(v.w);
    xo[t] = a;
    float ss = a.x*a.x + a.y*a.y + a.z*a.z + a.w*a.w;
    __shared__ float red[4];
    #pragma unroll
    for (int o = 16; o > 0; o >>= 1) ss += __shfl_xor_sync(0xffffffffu, ss, o);
    if ((t & 31) == 0) red[t >> 5] = ss;
    __syncthreads();
    if (t == 0) g_kk[row] = red[0] + red[1] + red[2] + red[3];
}

// ============================================================
// 2) SGEMM, A pre-packed to (a,a) pairs in SMEM
// ============================================================
#define BM 128
#define BN 128
#define BK 8

__global__ __launch_bounds__(256) void gemm_kernel(const float* __restrict__ W) {
    __shared__ __align__(16) u64   As2[BK][BM];   // (a,a) pairs, 8KB
    __shared__ __align__(16) float Bs[BK][BN];    // 4KB
    int tid = threadIdx.x;
    int bn = blockIdx.x;
    int bm = blockIdx.y;

    int lr = tid >> 1;
    int lc = (tid & 1) * 4;
    const float* Ag = g_xact + ((size_t)bm * BM + lr) * DD + lc;
    const float* Bg = W      + ((size_t)bn * BN + lr) * DD + lc;

    int tx = tid & 15, ty = tid >> 4;
    int r0 = ty * 8, c0 = tx * 8;

    u64 acc2[8][4];
    #pragma unroll
    for (int i = 0; i < 8; i++)
        #pragma unroll
        for (int j = 0; j < 4; j++) acc2[i][j] = 0ull;

    for (int k0 = 0; k0 < DD; k0 += BK) {
        float4 av = *reinterpret_cast<const float4*>(Ag + k0);
        float4 bv = *reinterpret_cast<const float4*>(Bg + k0);
        As2[lc + 0][lr] = pk2(av.x, av.x);
        As2[lc + 1][lr] = pk2(av.y, av.y);
        As2[lc + 2][lr] = pk2(av.z, av.z);
        As2[lc + 3][lr] = pk2(av.w, av.w);
        Bs[lc + 0][lr] = bv.x; Bs[lc + 1][lr] = bv.y;
        Bs[lc + 2][lr] = bv.z; Bs[lc + 3][lr] = bv.w;
        __syncthreads();
        #pragma unroll
        for (int k = 0; k < BK; k++) {
            ulonglong2 aa0 = *reinterpret_cast<const ulonglong2*>(&As2[k][r0]);
            ulonglong2 aa1 = *reinterpret_cast<const ulonglong2*>(&As2[k][r0 + 2]);
            ulonglong2 aa2 = *reinterpret_cast<const ulonglong2*>(&As2[k][r0 + 4]);
            ulonglong2 aa3 = *reinterpret_cast<const ulonglong2*>(&As2[k][r0 + 6]);
            ulonglong2 bv0 = *reinterpret_cast<const ulonglong2*>(&Bs[k][c0]);
            ulonglong2 bv1 = *reinterpret_cast<const ulonglong2*>(&Bs[k][c0 + 4]);
            u64 ap[8] = {aa0.x, aa0.y, aa1.x, aa1.y, aa2.x, aa2.y, aa3.x, aa3.y};
            u64 bp[4] = {bv0.x, bv0.y, bv1.x, bv1.y};
            #pragma unroll
            for (int i = 0; i < 8; i++)
                #pragma unroll
                for (int j = 0; j < 4; j++)
                    acc2[i][j] = ffma2(ap[i], bp[j], acc2[i][j]);
        }
        __syncthreads();
    }

    #pragma unroll
    for (int i = 0; i < 8; i++) {
        float* cp = g_stat + ((size_t)bm * BM + r0 + i) * DD + bn * BN + c0;
        ulonglong2 w0, w1;
        w0.x = acc2[i][0]; w0.y = acc2[i][1];
        w1.x = acc2[i][2]; w1.y = acc2[i][3];
        *reinterpret_cast<ulonglong2*>(cp)     = w0;
        *reinterpret_cast<ulonglong2*>(cp + 4) = w1;
    }
}

// ============================================================
// 3) scan: one WARP per 2 adjacent columns (unchanged from round 3)
// ============================================================
__global__ __launch_bounds__(256) void scan_kernel(const float* __restrict__ eta_p,
                                                   const float* __restrict__ laml_p) {
    float beta = eta_p[0];
    float lam = 1.0f / (1.0f + expf(-laml_p[0]));
    float invlam = 1.0f / lam;
    float lam64 = lam;
    #pragma unroll
    for (int i = 0; i < 6; i++) lam64 *= lam64;
    u64 lam64p = pk2(lam64, lam64);

    int wid  = threadIdx.x >> 5;
    int lane = threadIdx.x & 31;
    int b    = blockIdx.x >> 5;                         // 32 blocks per batch
    int cp   = ((blockIdx.x & 31) << 3) + wid;          // column pair 0..255
    int col  = cp << 1;

    const float* xb = g_xact + (size_t)b * LL * DD + 2 * lane;
    const float* vb = g_stat + (size_t)b * LL * DD + col;
    const float* kb = g_kk   + (size_t)b * LL;
    float*       ob = g_odyn + (size_t)b * LL * DD + col;

    u64 S2[16];
    #pragma unroll
    for (int i = 0; i < 16; i++) S2[i] = 0ull;

    u64 KA[8], KB[8];
    #pragma unroll
    for (int p = 0; p < 8; p++)
        KA[p] = *reinterpret_cast<const u64*>(xb + 64 * p);
    float2 vA = *reinterpret_cast<const float2*>(vb);
    float  kkA = kb[0];
    float2 vB; float kkB;

    float p = lam, pinv = invlam;

#define SCAN_STEP(KC, VV, KK, TT) do {                                        \
        u64 a0a = 0ull, a0b = 0ull, a1a = 0ull, a1b = 0ull;                   \
        _Pragma("unroll")                                                     \
        for (int q = 0; q < 4; q++) {                                         \
            a0a = ffma2(KC[q], S2[2*q],   a0a);                               \
            a1a = ffma2(KC[q], S2[2*q+1], a1a);                               \
        }                                                                     \
        _Pragma("unroll")                                                     \
        for (int q = 4; q < 8; q++) {                                         \
            a0b = ffma2(KC[q], S2[2*q],   a0b);                               \
            a1b = ffma2(KC[q], S2[2*q+1], a1b);                               \
        }                                                                     \
        float y0, y1, y2, y3, z0, z1, z2, z3;                                 \
        upk2(a0a, y0, y1); upk2(a0b, y2, y3);                                 \
        upk2(a1a, z0, z1); upk2(a1b, z2, z3);                                 \
        float d0 = (y0 + y1) + (y2 + y3);                                     \
        float d1 = (z0 + z1) + (z2 + z3);                                     \
        _Pragma("unroll")                                                     \
        for (int o = 1; o < 32; o <<= 1) {                                    \
            d0 += __shfl_xor_sync(0xffffffffu, d0, o);                        \
            d1 += __shfl_xor_sync(0xffffffffu, d1, o);                        \
        }                                                                     \
        float pd0 = p * d0,  pd1 = p * d1;                                    \
        float ve0 = beta * ((VV).x - pd0);                                    \
        float ve1 = beta * ((VV).y - pd1);                                    \
        if (lane == 0) {                                                      \
            float2 oo; oo.x = pd0 + (KK) * ve0; oo.y = pd1 + (KK) * ve1;      \
            *reinterpret_cast<float2*>(ob + (size_t)(TT) * DD) = oo;          \
        }                                                                     \
        u64 w0 = pk2(pinv * ve0, pinv * ve0);                                 \
        u64 w1 = pk2(pinv * ve1, pinv * ve1);                                 \
        _Pragma("unroll")                                                     \
        for (int q = 0; q < 8; q++) {                                         \
            S2[2*q]   = ffma2(KC[q], w0, S2[2*q]);                            \
            S2[2*q+1] = ffma2(KC[q], w1, S2[2*q+1]);                          \
        }                                                                     \
    } while (0)

    for (int t = 0; t < LL; t += 2) {
        {
            const float* kp = xb + (size_t)(t + 1) * DD;
            #pragma unroll
            for (int q = 0; q < 8; q++)
                KB[q] = *reinterpret_cast<const u64*>(kp + 64 * q);
            vB  = *reinterpret_cast<const float2*>(vb + (size_t)(t + 1) * DD);
            kkB = kb[t + 1];
        }

        SCAN_STEP(KA, vA, kkA, t);
        p *= lam; pinv *= invlam;        // t even: never a chunk boundary

        {
            int tn = (t + 2 < LL) ? (t + 2) : t;
            const float* kp = xb + (size_t)tn * DD;
            #pragma unroll
            for (int q = 0; q < 8; q++)
                KA[q] = *reinterpret_cast<const u64*>(kp + 64 * q);
            vA  = *reinterpret_cast<const float2*>(vb + (size_t)tn * DD);
            kkA = kb[tn];
        }

        SCAN_STEP(KB, vB, kkB, t + 1);
        if ((t & 63) == 62) {
            #pragma unroll
            for (int i = 0; i < 16; i++) S2[i] = fmul2(S2[i], lam64p);
            p = lam; pinv = invlam;
        } else {
            p *= lam; pinv *= invlam;
        }
    }
#undef SCAN_STEP
}

// ============================================================
// 4) LayerNorm
// ============================================================
__global__ void ln_kernel(const float* __restrict__ gamma,
                          const float* __restrict__ lbeta,
                          float* __restrict__ out) {
    int row = blockIdx.x;
    int t = threadIdx.x;
    const float4* sp = reinterpret_cast<const float4*>(g_stat + (size_t)row * DD);
    const float4* op = reinterpret_cast<const float4*>(g_odyn + (size_t)row * DD);
    float4 sv = sp[t], ov = op[t];
    float4 y;
    y.x = sv.x + ov.x; y.y = sv.y + ov.y; y.z = sv.z + ov.z; y.w = sv.w + ov.w;

    float sum = y.x + y.y + y.z + y.w;
    float sq  = y.x*y.x + y.y*y.y + y.z*y.z + y.w*y.w;

    __shared__ float r1[4], r2[4];
    #pragma unroll
    for (int o = 16; o > 0; o >>= 1) {
        sum += __shfl_xor_sync(0xffffffffu, sum, o);
        sq  += __shfl_xor_sync(0xffffffffu, sq, o);
    }
    if ((t & 31) == 0) { r1[t >> 5] = sum; r2[t >> 5] = sq; }
    __syncthreads();
    __shared__ float smu, srs;
    if (t == 0) {
        float ts = r1[0] + r1[1] + r1[2] + r1[3];
        float tq = r2[0] + r2[1] + r2[2] + r2[3];
        float mu = ts * (1.0f / DD);
        float var = tq * (1.0f / DD) - mu * mu;
        smu = mu;
        srs = rsqrtf(var + 1e-5f);
    }
    __syncthreads();
    float mu = smu, rs = srs;

    const float4* gp = reinterpret_cast<const float4*>(gamma);
    const float4* bp = reinterpret_cast<const float4*>(lbeta);
    float4 gv = gp[t], bv = bp[t];
    float4 r;
    r.x = (y.x - mu) * rs * gv.x + bv.x;
    r.y = (y.y - mu) * rs * gv.y + bv.y;
    r.z = (y.z - mu) * rs * gv.z + bv.z;
    r.w = (y.w - mu) * rs * gv.w + bv.w;
    reinterpret_cast<float4*>(out + (size_t)row * DD)[t] = r;
}

// ============================================================
extern "C" void kernel_launch(void* const* d_in, const int* in_sizes, int n_in,
                              void* d_out, int out_size) {
    const float* x     = (const float*)d_in[0];
    const float* W     = (const float*)d_in[1];
    const float* eta   = (const float*)d_in[2];
    const float* laml  = (const float*)d_in[3];
    const float* gamma = (const float*)d_in[4];
    const float* lbeta = (const float*)d_in[5];
    float* out = (float*)d_out;

    prep_kernel<<<NROW, 128>>>(x);
    gemm_kernel<<<dim3(DD / BN, NROW / BM), 256>>>(W);
    scan_kernel<<<128, 256>>>(eta, laml);
    ln_kernel<<<NROW, 128>>>(gamma, lbeta, out);
}

// round 5
// speedup vs baseline: 1.0504x; 1.0422x over previous
#include <cuda_runtime.h>
#include <math.h>

#define BB 4
#define LL 2048
#define DD 512
#define NROW (BB*LL)

typedef unsigned long long u64;

// ---- packed fp32x2 helpers ----
__device__ __forceinline__ u64 pk2(float x, float y) {
    u64 r; asm("mov.b64 %0, {%1, %2};" : "=l"(r) : "f"(x), "f"(y)); return r;
}
__device__ __forceinline__ void upk2(u64 v, float& x, float& y) {
    asm("mov.b64 {%0, %1}, %2;" : "=f"(x), "=f"(y) : "l"(v));
}
__device__ __forceinline__ u64 ffma2(u64 a, u64 b, u64 c) {
    u64 d; asm("fma.rn.f32x2 %0, %1, %2, %3;" : "=l"(d) : "l"(a), "l"(b), "l"(c)); return d;
}
__device__ __forceinline__ u64 fmul2(u64 a, u64 b) {
    u64 d; asm("mul.rn.f32x2 %0, %1, %2;" : "=l"(d) : "l"(a), "l"(b)); return d;
}

// ---- fast tanh ----
__device__ __forceinline__ float fast_tanh(float x) {
    float ax = fabsf(x);
    float e  = __expf(2.0f * ax);
    float t  = 1.0f - __fdividef(2.0f, e + 1.0f);
    return copysignf(t, x);
}

// ---- scratch ----
__device__ float g_xact[NROW*DD];
__device__ float g_stat[NROW*DD];
__device__ float g_odyn[NROW*DD];
__device__ float g_kk[NROW];
__device__ float g_kadj[NROW];   // kadj[b*LL+t] = k_t . k_{t+1} (0 at t=LL-1)

// ---- ncu alignment markers (shift profiled launch index) ----
__global__ void marker_a() {}
__global__ void marker_b() {}

// ============================================================
// 1) prep: x_act = tanh(x), kk[row] = sum(x_act^2)
// ============================================================
__global__ void prep_kernel(const float* __restrict__ x) {
    int row = blockIdx.x;
    int t = threadIdx.x;
    const float4* xin = reinterpret_cast<const float4*>(x + (size_t)row * DD);
    float4* xo = reinterpret_cast<float4*>(g_xact + (size_t)row * DD);
    float4 v = xin[t];
    float4 a;
    a.x = fast_tanh(v.x); a.y = fast_tanh(v.y);
    a.z = fast_tanh(v.z); a.w = fast_tanh(v.w);
    xo[t] = a;
    float ss = a.x*a.x + a.y*a.y + a.z*a.z + a.w*a.w;
    __shared__ float red[4];
    #pragma unroll
    for (int o = 16; o > 0; o >>= 1) ss += __shfl_xor_sync(0xffffffffu, ss, o);
    if ((t & 31) == 0) red[t >> 5] = ss;
    __syncthreads();
    if (t == 0) g_kk[row] = red[0] + red[1] + red[2] + red[3];
}

// ============================================================
// 1b) kadj: adjacent-row dot products of x_act
// ============================================================
__global__ void kadj_kernel() {
    int r = blockIdx.x;
    int t = threadIdx.x;
    int pos = r % LL;
    float s = 0.f;
    if (pos != LL - 1) {
        const float4* a = reinterpret_cast<const float4*>(g_xact + (size_t)r * DD);
        const float4* c = reinterpret_cast<const float4*>(g_xact + (size_t)(r + 1) * DD);
        float4 xa = a[t], xc = c[t];
        s = xa.x*xc.x + xa.y*xc.y + xa.z*xc.z + xa.w*xc.w;
    }
    __shared__ float red[4];
    #pragma unroll
    for (int o = 16; o > 0; o >>= 1) s += __shfl_xor_sync(0xffffffffu, s, o);
    if ((t & 31) == 0) red[t >> 5] = s;
    __syncthreads();
    if (t == 0) g_kadj[r] = red[0] + red[1] + red[2] + red[3];
}

// ============================================================
// 2) SGEMM (unchanged)
// ============================================================
#define BM 128
#define BN 128
#define BK 8

__global__ __launch_bounds__(256) void gemm_kernel(const float* __restrict__ W) {
    __shared__ __align__(16) u64   As2[BK][BM];
    __shared__ __align__(16) float Bs[BK][BN];
    int tid = threadIdx.x;
    int bn = blockIdx.x;
    int bm = blockIdx.y;

    int lr = tid >> 1;
    int lc = (tid & 1) * 4;
    const float* Ag = g_xact + ((size_t)bm * BM + lr) * DD + lc;
    const float* Bg = W      + ((size_t)bn * BN + lr) * DD + lc;

    int tx = tid & 15, ty = tid >> 4;
    int r0 = ty * 8, c0 = tx * 8;

    u64 acc2[8][4];
    #pragma unroll
    for (int i = 0; i < 8; i++)
        #pragma unroll
        for (int j = 0; j < 4; j++) acc2[i][j] = 0ull;

    for (int k0 = 0; k0 < DD; k0 += BK) {
        float4 av = *reinterpret_cast<const float4*>(Ag + k0);
        float4 bv = *reinterpret_cast<const float4*>(Bg + k0);
        As2[lc + 0][lr] = pk2(av.x, av.x);
        As2[lc + 1][lr] = pk2(av.y, av.y);
        As2[lc + 2][lr] = pk2(av.z, av.z);
        As2[lc + 3][lr] = pk2(av.w, av.w);
        Bs[lc + 0][lr] = bv.x; Bs[lc + 1][lr] = bv.y;
        Bs[lc + 2][lr] = bv.z; Bs[lc + 3][lr] = bv.w;
        __syncthreads();
        #pragma unroll
        for (int k = 0; k < BK; k++) {
            ulonglong2 aa0 = *reinterpret_cast<const ulonglong2*>(&As2[k][r0]);
            ulonglong2 aa1 = *reinterpret_cast<const ulonglong2*>(&As2[k][r0 + 2]);
            ulonglong2 aa2 = *reinterpret_cast<const ulonglong2*>(&As2[k][r0 + 4]);
            ulonglong2 aa3 = *reinterpret_cast<const ulonglong2*>(&As2[k][r0 + 6]);
            ulonglong2 bv0 = *reinterpret_cast<const ulonglong2*>(&Bs[k][c0]);
            ulonglong2 bv1 = *reinterpret_cast<const ulonglong2*>(&Bs[k][c0 + 4]);
            u64 ap[8] = {aa0.x, aa0.y, aa1.x, aa1.y, aa2.x, aa2.y, aa3.x, aa3.y};
            u64 bp[4] = {bv0.x, bv0.y, bv1.x, bv1.y};
            #pragma unroll
            for (int i = 0; i < 8; i++)
                #pragma unroll
                for (int j = 0; j < 4; j++)
                    acc2[i][j] = ffma2(ap[i], bp[j], acc2[i][j]);
        }
        __syncthreads();
    }

    #pragma unroll
    for (int i = 0; i < 8; i++) {
        float* cp = g_stat + ((size_t)bm * BM + r0 + i) * DD + bn * BN + c0;
        ulonglong2 w0, w1;
        w0.x = acc2[i][0]; w0.y = acc2[i][1];
        w1.x = acc2[i][2]; w1.y = acc2[i][3];
        *reinterpret_cast<ulonglong2*>(cp)     = w0;
        *reinterpret_cast<ulonglong2*>(cp + 4) = w1;
    }
}

// ============================================================
// 3) scan with PIPELINED REDUCTION:
//    d_t = k_t^T S'_{t-1} = [k_t^T S'_{t-2}] + (k_t.k_{t-1}) w_{t-1}
//    The bracketed partial (and its 5-shfl reduce) is computed one
//    step EARLY against the pre-update state; the scalar cross term
//    kadj is precomputed. SHFL latency overlaps update+prefetch.
//    One warp per 2 columns; manual unroll x2 ping-pong k buffers.
// ============================================================
__global__ __launch_bounds__(256) void scan_kernel(const float* __restrict__ eta_p,
                                                   const float* __restrict__ laml_p) {
    float beta = eta_p[0];
    float lam = 1.0f / (1.0f + expf(-laml_p[0]));
    float invlam = 1.0f / lam;
    float lam64 = lam;
    #pragma unroll
    for (int i = 0; i < 6; i++) lam64 *= lam64;
    u64 lam64p = pk2(lam64, lam64);

    int wid  = threadIdx.x >> 5;
    int lane = threadIdx.x & 31;
    int b    = blockIdx.x >> 5;
    int cp   = ((blockIdx.x & 31) << 3) + wid;
    int col  = cp << 1;

    const float* __restrict__ xb = g_xact + (size_t)b * LL * DD + 2 * lane;
    const float* __restrict__ vb = g_stat + (size_t)b * LL * DD + col;
    const float* __restrict__ kb = g_kk   + (size_t)b * LL;
    const float* __restrict__ ab = g_kadj + (size_t)b * LL;
    float*       __restrict__ ob = g_odyn + (size_t)b * LL * DD + col;

    u64 S2[16];
    #pragma unroll
    for (int i = 0; i < 16; i++) S2[i] = 0ull;

    u64 KA[8], KB[8];
    #pragma unroll
    for (int q = 0; q < 8; q++) {
        KA[q] = *reinterpret_cast<const u64*>(xb + 64 * q);
        KB[q] = *reinterpret_cast<const u64*>(xb + (size_t)DD + 64 * q);
    }
    float2 vcur = *reinterpret_cast<const float2*>(vb);
    float  kkcur = kb[0];

    float rp0 = 0.f, rp1 = 0.f;          // reduced partial for current body
    float w0prev = 0.f, w1prev = 0.f;    // w of previous step
    float kadjprev = 0.f;                // k_{t-1}.k_t
    float sfix = 1.0f;                   // lam^64 on post-boundary step
    float p = lam, pinv = invlam;

#define BODY(T, CUR, NXT, ISODD) do {                                          \
        float d0 = sfix * fmaf(kadjprev, w0prev, rp0);                         \
        float d1 = sfix * fmaf(kadjprev, w1prev, rp1);                         \
        float pd0 = p * d0, pd1 = p * d1;                                      \
        float ve0 = beta * (vcur.x - pd0);                                     \
        float ve1 = beta * (vcur.y - pd1);                                     \
        if (lane == 0) {                                                       \
            float2 oo;                                                         \
            oo.x = fmaf(kkcur, ve0, pd0);                                      \
            oo.y = fmaf(kkcur, ve1, pd1);                                      \
            *reinterpret_cast<float2*>(ob + (size_t)(T) * DD) = oo;            \
        }                                                                      \
        float w0 = pinv * ve0, w1 = pinv * ve1;                                \
        /* local partial for step T+1 against PRE-update state */              \
        u64 q0 = 0ull, q1 = 0ull, q2 = 0ull, q3 = 0ull;                        \
        _Pragma("unroll")                                                      \
        for (int q = 0; q < 4; q++) {                                          \
            q0 = ffma2(NXT[q], S2[2*q],   q0);                                 \
            q1 = ffma2(NXT[q], S2[2*q+1], q1);                                 \
        }                                                                      \
        _Pragma("unroll")                                                      \
        for (int q = 4; q < 8; q++) {                                          \
            q2 = ffma2(NXT[q], S2[2*q],   q2);                                 \
            q3 = ffma2(NXT[q], S2[2*q+1], q3);                                 \
        }                                                                      \
        float y0, y1, y2, y3, z0, z1, z2, z3;                                  \
        upk2(q0, y0, y1); upk2(q2, y2, y3);                                    \
        upk2(q1, z0, z1); upk2(q3, z2, z3);                                    \
        float pl0 = (y0 + y1) + (y2 + y3);                                     \
        float pl1 = (z0 + z1) + (z2 + z3);                                     \
        _Pragma("unroll")                                                      \
        for (int o = 1; o < 32; o <<= 1) {                                     \
            pl0 += __shfl_xor_sync(0xffffffffu, pl0, o);                       \
            pl1 += __shfl_xor_sync(0xffffffffu, pl1, o);                       \
        }                                                                      \
        /* apply update T: S += k_T * w_T */                                   \
        u64 wp0 = pk2(w0, w0), wp1 = pk2(w1, w1);                              \
        _Pragma("unroll")                                                      \
        for (int q = 0; q < 8; q++) {                                          \
            S2[2*q]   = ffma2(CUR[q], wp0, S2[2*q]);                           \
            S2[2*q+1] = ffma2(CUR[q], wp1, S2[2*q+1]);                         \
        }                                                                      \
        /* prefetch k_{T+2} into CUR (last use above) */                       \
        {                                                                      \
            int tk = ((T) + 2 < LL) ? (T) + 2 : LL - 1;                        \
            const float* kp = xb + (size_t)tk * DD;                            \
            _Pragma("unroll")                                                  \
            for (int q = 0; q < 8; q++)                                        \
                CUR[q] = *reinterpret_cast<const u64*>(kp + 64 * q);           \
        }                                                                      \
        {                                                                      \
            int tv = ((T) + 1 < LL) ? (T) + 1 : LL - 1;                        \
            vcur  = *reinterpret_cast<const float2*>(vb + (size_t)tv * DD);    \
            kkcur = kb[tv];                                                    \
        }                                                                      \
        kadjprev = ab[((T) < LL - 1) ? (T) : LL - 2];                          \
        rp0 = pl0; rp1 = pl1; w0prev = w0; w1prev = w1;                        \
        if (ISODD && (((T) & 63) == 63)) {                                     \
            _Pragma("unroll")                                                  \
            for (int i = 0; i < 16; i++) S2[i] = fmul2(S2[i], lam64p);         \
            p = lam; pinv = invlam; sfix = lam64;                              \
        } else {                                                               \
            p *= lam; pinv *= invlam; sfix = 1.0f;                             \
        }                                                                      \
    } while (0)

    #pragma unroll 1
    for (int t = 0; t < LL; t += 2) {
        BODY(t,     KA, KB, 0);
        BODY(t + 1, KB, KA, 1);
    }
#undef BODY
}

// ============================================================
// 4) LayerNorm
// ============================================================
__global__ void ln_kernel(const float* __restrict__ gamma,
                          const float* __restrict__ lbeta,
                          float* __restrict__ out) {
    int row = blockIdx.x;
    int t = threadIdx.x;
    const float4* sp = reinterpret_cast<const float4*>(g_stat + (size_t)row * DD);
    const float4* op = reinterpret_cast<const float4*>(g_odyn + (size_t)row * DD);
    float4 sv = sp[t], ov = op[t];
    float4 y;
    y.x = sv.x + ov.x; y.y = sv.y + ov.y; y.z = sv.z + ov.z; y.w = sv.w + ov.w;

    float sum = y.x + y.y + y.z + y.w;
    float sq  = y.x*y.x + y.y*y.y + y.z*y.z + y.w*y.w;

    __shared__ float r1[4], r2[4];
    #pragma unroll
    for (int o = 16; o > 0; o >>= 1) {
        sum += __shfl_xor_sync(0xffffffffu, sum, o);
        sq  += __shfl_xor_sync(0xffffffffu, sq, o);
    }
    if ((t & 31) == 0) { r1[t >> 5] = sum; r2[t >> 5] = sq; }
    __syncthreads();
    __shared__ float smu, srs;
    if (t == 0) {
        float ts = r1[0] + r1[1] + r1[2] + r1[3];
        float tq = r2[0] + r2[1] + r2[2] + r2[3];
        float mu = ts * (1.0f / DD);
        float var = tq * (1.0f / DD) - mu * mu;
        smu = mu;
        srs = rsqrtf(var + 1e-5f);
    }
    __syncthreads();
    float mu = smu, rs = srs;

    const float4* gp = reinterpret_cast<const float4*>(gamma);
    const float4* bp = reinterpret_cast<const float4*>(lbeta);
    float4 gv = gp[t], bv = bp[t];
    float4 r;
    r.x = (y.x - mu) * rs * gv.x + bv.x;
    r.y = (y.y - mu) * rs * gv.y + bv.y;
    r.z = (y.z - mu) * rs * gv.z + bv.z;
    r.w = (y.w - mu) * rs * gv.w + bv.w;
    reinterpret_cast<float4*>(out + (size_t)row * DD)[t] = r;
}

// ============================================================
extern "C" void kernel_launch(void* const* d_in, const int* in_sizes, int n_in,
                              void* d_out, int out_size) {
    const float* x     = (const float*)d_in[0];
    const float* W     = (const float*)d_in[1];
    const float* eta   = (const float*)d_in[2];
    const float* laml  = (const float*)d_in[3];
    const float* gamma = (const float*)d_in[4];
    const float* lbeta = (const float*)d_in[5];
    float* out = (float*)d_out;

    // markers shift ncu's profiled launch (-s 5) onto scan_kernel (index 5)
    marker_a<<<1, 32>>>();
    marker_b<<<1, 32>>>();
    prep_kernel<<<NROW, 128>>>(x);
    kadj_kernel<<<NROW, 128>>>();
    gemm_kernel<<<dim3(DD / BN, NROW / BM), 256>>>(W);
    scan_kernel<<<128, 256>>>(eta, laml);
    ln_kernel<<<NROW, 128>>>(gamma, lbeta, out);
}

// round 6
// speedup vs baseline: 1.4940x; 1.4223x over previous
#include <cuda_runtime.h>
#include <math.h>

#define BB 4
#define LL 2048
#define DD 512
#define NROW (BB*LL)

typedef unsigned long long u64;

// ---- packed fp32x2 helpers ----
__device__ __forceinline__ u64 pk2(float x, float y) {
    u64 r; asm("mov.b64 %0, {%1, %2};" : "=l"(r) : "f"(x), "f"(y)); return r;
}
__device__ __forceinline__ void upk2(u64 v, float& x, float& y) {
    asm("mov.b64 {%0, %1}, %2;" : "=f"(x), "=f"(y) : "l"(v));
}
__device__ __forceinline__ u64 ffma2(u64 a, u64 b, u64 c) {
    u64 d; asm("fma.rn.f32x2 %0, %1, %2, %3;" : "=l"(d) : "l"(a), "l"(b), "l"(c)); return d;
}
__device__ __forceinline__ u64 fadd2(u64 a, u64 b) {
    u64 d; asm("add.rn.f32x2 %0, %1, %2;" : "=l"(d) : "l"(a), "l"(b)); return d;
}
__device__ __forceinline__ u64 fmul2(u64 a, u64 b) {
    u64 d; asm("mul.rn.f32x2 %0, %1, %2;" : "=l"(d) : "l"(a), "l"(b)); return d;
}

// ---- fast tanh ----
__device__ __forceinline__ float fast_tanh(float x) {
    float ax = fabsf(x);
    float e  = __expf(2.0f * ax);
    float t  = 1.0f - __fdividef(2.0f, e + 1.0f);
    return copysignf(t, x);
}

// ---- scratch ----
__device__ float g_xact[NROW*DD];
__device__ float g_stat[NROW*DD];
__device__ float g_odyn[NROW*DD];
__device__ float g_kk[NROW];
__device__ float g_kadj[NROW];   // kadj[b*LL+t] = k_t . k_{t+1} (0 at t=LL-1)

// ============================================================
// 1) prep
// ============================================================
__global__ void prep_kernel(const float* __restrict__ x) {
    int row = blockIdx.x;
    int t = threadIdx.x;
    const float4* xin = reinterpret_cast<const float4*>(x + (size_t)row * DD);
    float4* xo = reinterpret_cast<float4*>(g_xact + (size_t)row * DD);
    float4 v = xin[t];
    float4 a;
    a.x = fast_tanh(v.x); a.y = fast_tanh(v.y);
    a.z = fast_tanh(v.z); a.w = fast_tanh(v.w);
    xo[t] = a;
    float ss = a.x*a.x + a.y*a.y + a.z*a.z + a.w*a.w;
    __shared__ float red[4];
    #pragma unroll
    for (int o = 16; o > 0; o >>= 1) ss += __shfl_xor_sync(0xffffffffu, ss, o);
    if ((t & 31) == 0) red[t >> 5] = ss;
    __syncthreads();
    if (t == 0) g_kk[row] = red[0] + red[1] + red[2] + red[3];
}

// ============================================================
// 1b) kadj
// ============================================================
__global__ void kadj_kernel() {
    int r = blockIdx.x;
    int t = threadIdx.x;
    int pos = r % LL;
    float s = 0.f;
    if (pos != LL - 1) {
        const float4* a = reinterpret_cast<const float4*>(g_xact + (size_t)r * DD);
        const float4* c = reinterpret_cast<const float4*>(g_xact + (size_t)(r + 1) * DD);
        float4 xa = a[t], xc = c[t];
        s = xa.x*xc.x + xa.y*xc.y + xa.z*xc.z + xa.w*xc.w;
    }
    __shared__ float red[4];
    #pragma unroll
    for (int o = 16; o > 0; o >>= 1) s += __shfl_xor_sync(0xffffffffu, s, o);
    if ((t & 31) == 0) red[t >> 5] = s;
    __syncthreads();
    if (t == 0) g_kadj[r] = red[0] + red[1] + red[2] + red[3];
}

// ============================================================
// 2) SGEMM (unchanged)
// ============================================================
#define BM 128
#define BN 128
#define BK 8

__global__ __launch_bounds__(256) void gemm_kernel(const float* __restrict__ W) {
    __shared__ __align__(16) u64   As2[BK][BM];
    __shared__ __align__(16) float Bs[BK][BN];
    int tid = threadIdx.x;
    int bn = blockIdx.x;
    int bm = blockIdx.y;

    int lr = tid >> 1;
    int lc = (tid & 1) * 4;
    const float* Ag = g_xact + ((size_t)bm * BM + lr) * DD + lc;
    const float* Bg = W      + ((size_t)bn * BN + lr) * DD + lc;

    int tx = tid & 15, ty = tid >> 4;
    int r0 = ty * 8, c0 = tx * 8;

    u64 acc2[8][4];
    #pragma unroll
    for (int i = 0; i < 8; i++)
        #pragma unroll
        for (int j = 0; j < 4; j++) acc2[i][j] = 0ull;

    for (int k0 = 0; k0 < DD; k0 += BK) {
        float4 av = *reinterpret_cast<const float4*>(Ag + k0);
        float4 bv = *reinterpret_cast<const float4*>(Bg + k0);
        As2[lc + 0][lr] = pk2(av.x, av.x);
        As2[lc + 1][lr] = pk2(av.y, av.y);
        As2[lc + 2][lr] = pk2(av.z, av.z);
        As2[lc + 3][lr] = pk2(av.w, av.w);
        Bs[lc + 0][lr] = bv.x; Bs[lc + 1][lr] = bv.y;
        Bs[lc + 2][lr] = bv.z; Bs[lc + 3][lr] = bv.w;
        __syncthreads();
        #pragma unroll
        for (int k = 0; k < BK; k++) {
            ulonglong2 aa0 = *reinterpret_cast<const ulonglong2*>(&As2[k][r0]);
            ulonglong2 aa1 = *reinterpret_cast<const ulonglong2*>(&As2[k][r0 + 2]);
            ulonglong2 aa2 = *reinterpret_cast<const ulonglong2*>(&As2[k][r0 + 4]);
            ulonglong2 aa3 = *reinterpret_cast<const ulonglong2*>(&As2[k][r0 + 6]);
            ulonglong2 bv0 = *reinterpret_cast<const ulonglong2*>(&Bs[k][c0]);
            ulonglong2 bv1 = *reinterpret_cast<const ulonglong2*>(&Bs[k][c0 + 4]);
            u64 ap[8] = {aa0.x, aa0.y, aa1.x, aa1.y, aa2.x, aa2.y, aa3.x, aa3.y};
            u64 bp[4] = {bv0.x, bv0.y, bv1.x, bv1.y};
            #pragma unroll
            for (int i = 0; i < 8; i++)
                #pragma unroll
                for (int j = 0; j < 4; j++)
                    acc2[i][j] = ffma2(ap[i], bp[j], acc2[i][j]);
        }
        __syncthreads();
    }

    #pragma unroll
    for (int i = 0; i < 8; i++) {
        float* cp = g_stat + ((size_t)bm * BM + r0 + i) * DD + bn * BN + c0;
        ulonglong2 w0, w1;
        w0.x = acc2[i][0]; w0.y = acc2[i][1];
        w1.x = acc2[i][2]; w1.y = acc2[i][3];
        *reinterpret_cast<ulonglong2*>(cp)     = w0;
        *reinterpret_cast<ulonglong2*>(cp + 4) = w1;
    }
}

// ============================================================
// 3) scan: pipelined reduction + DEEP k prefetch (distance 3 bodies).
//    4 rotating k buffers; body T: consumes d_T (partial from body T-1
//    + precomputed kadj cross-term), dot-ahead for T+1 against
//    pre-update state, update with k_T, prefetch k_{T+4}.
// ============================================================
__global__ __launch_bounds__(256) void scan_kernel(const float* __restrict__ eta_p,
                                                   const float* __restrict__ laml_p) {
    float beta = eta_p[0];
    float lam = 1.0f / (1.0f + expf(-laml_p[0]));
    float invlam = 1.0f / lam;
    float lam64 = lam;
    #pragma unroll
    for (int i = 0; i < 6; i++) lam64 *= lam64;
    u64 lam64p = pk2(lam64, lam64);

    int wid  = threadIdx.x >> 5;
    int lane = threadIdx.x & 31;
    int b    = blockIdx.x >> 5;
    int cp   = ((blockIdx.x & 31) << 3) + wid;
    int col  = cp << 1;

    const float* __restrict__ xb = g_xact + (size_t)b * LL * DD + 2 * lane;
    const float* __restrict__ vb = g_stat + (size_t)b * LL * DD + col;
    const float* __restrict__ kb = g_kk   + (size_t)b * LL;
    const float* __restrict__ ab = g_kadj + (size_t)b * LL;
    float*       __restrict__ ob = g_odyn + (size_t)b * LL * DD + col;

    u64 S2[16];
    #pragma unroll
    for (int i = 0; i < 16; i++) S2[i] = 0ull;

    u64 K0[8], K1[8], K2[8], K3[8];
    #pragma unroll
    for (int q = 0; q < 8; q++) {
        K0[q] = *reinterpret_cast<const u64*>(xb + 64 * q);
        K1[q] = *reinterpret_cast<const u64*>(xb + (size_t)1 * DD + 64 * q);
        K2[q] = *reinterpret_cast<const u64*>(xb + (size_t)2 * DD + 64 * q);
        K3[q] = *reinterpret_cast<const u64*>(xb + (size_t)3 * DD + 64 * q);
    }
    float2 vbuf0 = *reinterpret_cast<const float2*>(vb);
    float2 vbuf1 = *reinterpret_cast<const float2*>(vb + (size_t)DD);
    float  kkbuf0 = kb[0], kkbuf1 = kb[1];
    float  kadjbuf0 = 0.f, kadjbuf1 = ab[0];

    float rp0 = 0.f, rp1 = 0.f;
    float w0prev = 0.f, w1prev = 0.f;
    float sfix = 1.0f;
    float p = lam, pinv = invlam;

// P selects the 0/1 slot of the v/kk/kadj double buffers (T parity).
#define BODY(T, CUR, NXT, VBUF, KKB, AJB) do {                                 \
        float d0 = sfix * fmaf(AJB, w0prev, rp0);                              \
        float d1 = sfix * fmaf(AJB, w1prev, rp1);                              \
        float pd0 = p * d0, pd1 = p * d1;                                      \
        float ve0 = beta * (VBUF.x - pd0);                                     \
        float ve1 = beta * (VBUF.y - pd1);                                     \
        if (lane == 0) {                                                       \
            float2 oo;                                                         \
            oo.x = fmaf(KKB, ve0, pd0);                                        \
            oo.y = fmaf(KKB, ve1, pd1);                                        \
            *reinterpret_cast<float2*>(ob + (size_t)(T) * DD) = oo;            \
        }                                                                      \
        float w0 = pinv * ve0, w1 = pinv * ve1;                                \
        /* dot-ahead for step T+1 against PRE-update state */                  \
        u64 q0 = 0ull, q1 = 0ull, q2 = 0ull, q3 = 0ull;                        \
        _Pragma("unroll")                                                      \
        for (int q = 0; q < 4; q++) {                                          \
            q0 = ffma2(NXT[q], S2[2*q],   q0);                                 \
            q1 = ffma2(NXT[q], S2[2*q+1], q1);                                 \
        }                                                                      \
        _Pragma("unroll")                                                      \
        for (int q = 4; q < 8; q++) {                                          \
            q2 = ffma2(NXT[q], S2[2*q],   q2);                                 \
            q3 = ffma2(NXT[q], S2[2*q+1], q3);                                 \
        }                                                                      \
        q0 = fadd2(q0, q2); q1 = fadd2(q1, q3);                                \
        float y0, y1, z0, z1;                                                  \
        upk2(q0, y0, y1); upk2(q1, z0, z1);                                    \
        float pl0 = y0 + y1, pl1 = z0 + z1;                                    \
        _Pragma("unroll")                                                      \
        for (int o = 1; o < 32; o <<= 1) {                                     \
            pl0 += __shfl_xor_sync(0xffffffffu, pl0, o);                       \
            pl1 += __shfl_xor_sync(0xffffffffu, pl1, o);                       \
        }                                                                      \
        /* update: S += k_T w_T */                                             \
        u64 wp0 = pk2(w0, w0), wp1 = pk2(w1, w1);                              \
        _Pragma("unroll")                                                      \
        for (int q = 0; q < 8; q++) {                                          \
            S2[2*q]   = ffma2(CUR[q], wp0, S2[2*q]);                           \
            S2[2*q+1] = ffma2(CUR[q], wp1, S2[2*q+1]);                         \
        }                                                                      \
        /* deep prefetch: k_{T+4} into CUR (consumed 3 bodies later) */        \
        {                                                                      \
            int tk = ((T) + 4 < LL) ? (T) + 4 : LL - 1;                        \
            const float* kp = xb + (size_t)tk * DD;                            \
            _Pragma("unroll")                                                  \
            for (int q = 0; q < 8; q++)                                        \
                CUR[q] = *reinterpret_cast<const u64*>(kp + 64 * q);           \
        }                                                                      \
        {                                                                      \
            int tv = ((T) + 2 < LL) ? (T) + 2 : LL - 1;                        \
            VBUF = *reinterpret_cast<const float2*>(vb + (size_t)tv * DD);     \
            KKB  = kb[tv];                                                     \
            AJB  = ab[((T) + 1 < LL) ? (T) + 1 : LL - 1];                      \
        }                                                                      \
        rp0 = pl0; rp1 = pl1; w0prev = w0; w1prev = w1;                        \
        if (((T) & 63) == 63) {                                                \
            _Pragma("unroll")                                                  \
            for (int i = 0; i < 16; i++) S2[i] = fmul2(S2[i], lam64p);         \
            p = lam; pinv = invlam; sfix = lam64;                              \
        } else {                                                               \
            p *= lam; pinv *= invlam; sfix = 1.0f;                             \
        }                                                                      \
    } while (0)

    #pragma unroll 1
    for (int t = 0; t < LL; t += 4) {
        BODY(t,     K0, K1, vbuf0, kkbuf0, kadjbuf0);
        BODY(t + 1, K1, K2, vbuf1, kkbuf1, kadjbuf1);
        BODY(t + 2, K2, K3, vbuf0, kkbuf0, kadjbuf0);
        BODY(t + 3, K3, K0, vbuf1, kkbuf1, kadjbuf1);
    }
#undef BODY
}

// ============================================================
// 4) LayerNorm
// ============================================================
__global__ void ln_kernel(const float* __restrict__ gamma,
                          const float* __restrict__ lbeta,
                          float* __restrict__ out) {
    int row = blockIdx.x;
    int t = threadIdx.x;
    const float4* sp = reinterpret_cast<const float4*>(g_stat + (size_t)row * DD);
    const float4* op = reinterpret_cast<const float4*>(g_odyn + (size_t)row * DD);
    float4 sv = sp[t], ov = op[t];
    float4 y;
    y.x = sv.x + ov.x; y.y = sv.y + ov.y; y.z = sv.z + ov.z; y.w = sv.w + ov.w;

    float sum = y.x + y.y + y.z + y.w;
    float sq  = y.x*y.x + y.y*y.y + y.z*y.z + y.w*y.w;

    __shared__ float r1[4], r2[4];
    #pragma unroll
    for (int o = 16; o > 0; o >>= 1) {
        sum += __shfl_xor_sync(0xffffffffu, sum, o);
        sq  += __shfl_xor_sync(0xffffffffu, sq, o);
    }
    if ((t & 31) == 0) { r1[t >> 5] = sum; r2[t >> 5] = sq; }
    __syncthreads();
    __shared__ float smu, srs;
    if (t == 0) {
        float ts = r1[0] + r1[1] + r1[2] + r1[3];
        float tq = r2[0] + r2[1] + r2[2] + r2[3];
        float mu = ts * (1.0f / DD);
        float var = tq * (1.0f / DD) - mu * mu;
        smu = mu;
        srs = rsqrtf(var + 1e-5f);
    }
    __syncthreads();
    float mu = smu, rs = srs;

    const float4* gp = reinterpret_cast<const float4*>(gamma);
    const float4* bp = reinterpret_cast<const float4*>(lbeta);
    float4 gv = gp[t], bv = bp[t];
    float4 r;
    r.x = (y.x - mu) * rs * gv.x + bv.x;
    r.y = (y.y - mu) * rs * gv.y + bv.y;
    r.z = (y.z - mu) * rs * gv.z + bv.z;
    r.w = (y.w - mu) * rs * gv.w + bv.w;
    reinterpret_cast<float4*>(out + (size_t)row * DD)[t] = r;
}

// ============================================================
extern "C" void kernel_launch(void* const* d_in, const int* in_sizes, int n_in,
                              void* d_out, int out_size) {
    const float* x     = (const float*)d_in[0];
    const float* W     = (const float*)d_in[1];
    const float* eta   = (const float*)d_in[2];
    const float* laml  = (const float*)d_in[3];
    const float* gamma = (const float*)d_in[4];
    const float* lbeta = (const float*)d_in[5];
    float* out = (float*)d_out;

    // launch order puts scan_kernel at index 3 (the launch ncu profiles)
    prep_kernel<<<NROW, 128>>>(x);
    kadj_kernel<<<NROW, 128>>>();
    gemm_kernel<<<dim3(DD / BN, NROW / BM), 256>>>(W);
    scan_kernel<<<128, 256>>>(eta, laml);
    ln_kernel<<<NROW, 128>>>(gamma, lbeta, out);
}

// round 7
// speedup vs baseline: 1.5378x; 1.0293x over previous
#include <cuda_runtime.h>
#include <math.h>

#define BB 4
#define LL 2048
#define DD 512
#define NROW (BB*LL)

typedef unsigned long long u64;

// ---- packed fp32x2 helpers ----
__device__ __forceinline__ u64 pk2(float x, float y) {
    u64 r; asm("mov.b64 %0, {%1, %2};" : "=l"(r) : "f"(x), "f"(y)); return r;
}
__device__ __forceinline__ void upk2(u64 v, float& x, float& y) {
    asm("mov.b64 {%0, %1}, %2;" : "=f"(x), "=f"(y) : "l"(v));
}
__device__ __forceinline__ u64 ffma2(u64 a, u64 b, u64 c) {
    u64 d; asm("fma.rn.f32x2 %0, %1, %2, %3;" : "=l"(d) : "l"(a), "l"(b), "l"(c)); return d;
}
__device__ __forceinline__ u64 fadd2(u64 a, u64 b) {
    u64 d; asm("add.rn.f32x2 %0, %1, %2;" : "=l"(d) : "l"(a), "l"(b)); return d;
}
__device__ __forceinline__ u64 fmul2(u64 a, u64 b) {
    u64 d; asm("mul.rn.f32x2 %0, %1, %2;" : "=l"(d) : "l"(a), "l"(b)); return d;
}

// ---- fast tanh ----
__device__ __forceinline__ float fast_tanh(float x) {
    float ax = fabsf(x);
    float e  = __expf(2.0f * ax);
    float t  = 1.0f - __fdividef(2.0f, e + 1.0f);
    return copysignf(t, x);
}

// ---- scratch ----
__device__ float g_xact[NROW*DD];
__device__ float g_stat[NROW*DD];
__device__ float g_odyn[NROW*DD];
__device__ float g_kk[NROW];
__device__ float g_kadj[NROW];   // kadj[b*LL+t] = k_t . k_{t+1} (0 at t=LL-1)

// ============================================================
// 1) prep
// ============================================================
__global__ void prep_kernel(const float* __restrict__ x) {
    int row = blockIdx.x;
    int t = threadIdx.x;
    const float4* xin = reinterpret_cast<const float4*>(x + (size_t)row * DD);
    float4* xo = reinterpret_cast<float4*>(g_xact + (size_t)row * DD);
    float4 v = xin[t];
    float4 a;
    a.x = fast_tanh(v.x); a.y = fast_tanh(v.y);
    a.z = fast_tanh(v.z); a.w = fast_tanh(v.w);
    xo[t] = a;
    float ss = a.x*a.x + a.y*a.y + a.z*a.z + a.w*a.w;
    __shared__ float red[4];
    #pragma unroll
    for (int o = 16; o > 0; o >>= 1) ss += __shfl_xor_sync(0xffffffffu, ss, o);
    if ((t & 31) == 0) red[t >> 5] = ss;
    __syncthreads();
    if (t == 0) g_kk[row] = red[0] + red[1] + red[2] + red[3];
}

// ============================================================
// 1b) kadj
// ============================================================
__global__ void kadj_kernel() {
    int r = blockIdx.x;
    int t = threadIdx.x;
    int pos = r % LL;
    float s = 0.f;
    if (pos != LL - 1) {
        const float4* a = reinterpret_cast<const float4*>(g_xact + (size_t)r * DD);
        const float4* c = reinterpret_cast<const float4*>(g_xact + (size_t)(r + 1) * DD);
        float4 xa = a[t], xc = c[t];
        s = xa.x*xc.x + xa.y*xc.y + xa.z*xc.z + xa.w*xc.w;
    }
    __shared__ float red[4];
    #pragma unroll
    for (int o = 16; o > 0; o >>= 1) s += __shfl_xor_sync(0xffffffffu, s, o);
    if ((t & 31) == 0) red[t >> 5] = s;
    __syncthreads();
    if (t == 0) g_kadj[r] = red[0] + red[1] + red[2] + red[3];
}

// ============================================================
// 2) SGEMM (unchanged)
// ============================================================
#define BM 128
#define BN 128
#define BK 8

__global__ __launch_bounds__(256) void gemm_kernel(const float* __restrict__ W) {
    __shared__ __align__(16) u64   As2[BK][BM];
    __shared__ __align__(16) float Bs[BK][BN];
    int tid = threadIdx.x;
    int bn = blockIdx.x;
    int bm = blockIdx.y;

    int lr = tid >> 1;
    int lc = (tid & 1) * 4;
    const float* Ag = g_xact + ((size_t)bm * BM + lr) * DD + lc;
    const float* Bg = W      + ((size_t)bn * BN + lr) * DD + lc;

    int tx = tid & 15, ty = tid >> 4;
    int r0 = ty * 8, c0 = tx * 8;

    u64 acc2[8][4];
    #pragma unroll
    for (int i = 0; i < 8; i++)
        #pragma unroll
        for (int j = 0; j < 4; j++) acc2[i][j] = 0ull;

    for (int k0 = 0; k0 < DD; k0 += BK) {
        float4 av = *reinterpret_cast<const float4*>(Ag + k0);
        float4 bv = *reinterpret_cast<const float4*>(Bg + k0);
        As2[lc + 0][lr] = pk2(av.x, av.x);
        As2[lc + 1][lr] = pk2(av.y, av.y);
        As2[lc + 2][lr] = pk2(av.z, av.z);
        As2[lc + 3][lr] = pk2(av.w, av.w);
        Bs[lc + 0][lr] = bv.x; Bs[lc + 1][lr] = bv.y;
        Bs[lc + 2][lr] = bv.z; Bs[lc + 3][lr] = bv.w;
        __syncthreads();
        #pragma unroll
        for (int k = 0; k < BK; k++) {
            ulonglong2 aa0 = *reinterpret_cast<const ulonglong2*>(&As2[k][r0]);
            ulonglong2 aa1 = *reinterpret_cast<const ulonglong2*>(&As2[k][r0 + 2]);
            ulonglong2 aa2 = *reinterpret_cast<const ulonglong2*>(&As2[k][r0 + 4]);
            ulonglong2 aa3 = *reinterpret_cast<const ulonglong2*>(&As2[k][r0 + 6]);
            ulonglong2 bv0 = *reinterpret_cast<const ulonglong2*>(&Bs[k][c0]);
            ulonglong2 bv1 = *reinterpret_cast<const ulonglong2*>(&Bs[k][c0 + 4]);
            u64 ap[8] = {aa0.x, aa0.y, aa1.x, aa1.y, aa2.x, aa2.y, aa3.x, aa3.y};
            u64 bp[4] = {bv0.x, bv0.y, bv1.x, bv1.y};
            #pragma unroll
            for (int i = 0; i < 8; i++)
                #pragma unroll
                for (int j = 0; j < 4; j++)
                    acc2[i][j] = ffma2(ap[i], bp[j], acc2[i][j]);
        }
        __syncthreads();
    }

    #pragma unroll
    for (int i = 0; i < 8; i++) {
        float* cp = g_stat + ((size_t)bm * BM + r0 + i) * DD + bn * BN + c0;
        ulonglong2 w0, w1;
        w0.x = acc2[i][0]; w0.y = acc2[i][1];
        w1.x = acc2[i][2]; w1.y = acc2[i][3];
        *reinterpret_cast<ulonglong2*>(cp)     = w0;
        *reinterpret_cast<ulonglong2*>(cp + 4) = w1;
    }
}

// ============================================================
// 3) scan: ONE COLUMN PER WARP (2048 warps = 128 blocks x 512thr,
//    4 warps/SMSP). Pipelined reduction + deep k prefetch as R6.
//    Lane owns rows 2*lane + 64p (8 u64); S = 8 u64/lane.
// ============================================================
__global__ __launch_bounds__(512) void scan_kernel(const float* __restrict__ eta_p,
                                                   const float* __restrict__ laml_p) {
    float beta = eta_p[0];
    float lam = 1.0f / (1.0f + expf(-laml_p[0]));
    float invlam = 1.0f / lam;
    float lam64 = lam;
    #pragma unroll
    for (int i = 0; i < 6; i++) lam64 *= lam64;
    u64 lam64p = pk2(lam64, lam64);

    int wid  = threadIdx.x >> 5;                 // 0..15
    int lane = threadIdx.x & 31;
    int b    = blockIdx.x >> 5;                  // 32 blocks per batch
    int col  = ((blockIdx.x & 31) << 4) + wid;   // 0..511

    const float* __restrict__ xb = g_xact + (size_t)b * LL * DD + 2 * lane;
    const float* __restrict__ vb = g_stat + (size_t)b * LL * DD + col;
    const float* __restrict__ kb = g_kk   + (size_t)b * LL;
    const float* __restrict__ ab = g_kadj + (size_t)b * LL;
    float*       __restrict__ ob = g_odyn + (size_t)b * LL * DD + col;

    // S2[p] = rows (64p + 2*lane, +1) of this column
    u64 S2[8];
    #pragma unroll
    for (int i = 0; i < 8; i++) S2[i] = 0ull;

    u64 K0[8], K1[8], K2[8], K3[8];
    #pragma unroll
    for (int q = 0; q < 8; q++) {
        K0[q] = *reinterpret_cast<const u64*>(xb + 64 * q);
        K1[q] = *reinterpret_cast<const u64*>(xb + (size_t)1 * DD + 64 * q);
        K2[q] = *reinterpret_cast<const u64*>(xb + (size_t)2 * DD + 64 * q);
        K3[q] = *reinterpret_cast<const u64*>(xb + (size_t)3 * DD + 64 * q);
    }
    float vbuf0 = vb[0];
    float vbuf1 = vb[(size_t)DD];
    float kkbuf0 = kb[0], kkbuf1 = kb[1];
    float kadjbuf0 = 0.f, kadjbuf1 = ab[0];

    float rp = 0.f;        // reduced partial (k_T^T S'_{T-2}), from body T-1
    float wprev = 0.f;
    float sfix = 1.0f;
    float p = lam, pinv = invlam;

#define BODY(T, CUR, NXT, VBUF, KKB, AJB) do {                                 \
        float d = sfix * fmaf(AJB, wprev, rp);                                 \
        float pd = p * d;                                                      \
        float ve = beta * (VBUF - pd);                                         \
        if (lane == 0) ob[(size_t)(T) * DD] = fmaf(KKB, ve, pd);               \
        float w = pinv * ve;                                                   \
        /* dot-ahead for step T+1 against PRE-update state */                  \
        u64 q0 = 0ull, q1 = 0ull;                                              \
        _Pragma("unroll")                                                      \
        for (int q = 0; q < 4; q++) q0 = ffma2(NXT[q], S2[q], q0);             \
        _Pragma("unroll")                                                      \
        for (int q = 4; q < 8; q++) q1 = ffma2(NXT[q], S2[q], q1);             \
        q0 = fadd2(q0, q1);                                                    \
        float y0, y1;                                                          \
        upk2(q0, y0, y1);                                                      \
        float pl = y0 + y1;                                                    \
        pl += __shfl_xor_sync(0xffffffffu, pl, 1);                             \
        pl += __shfl_xor_sync(0xffffffffu, pl, 2);                             \
        pl += __shfl_xor_sync(0xffffffffu, pl, 4);                             \
        pl += __shfl_xor_sync(0xffffffffu, pl, 8);                             \
        pl += __shfl_xor_sync(0xffffffffu, pl, 16);                            \
        /* update: S += k_T w_T */                                             \
        u64 wp = pk2(w, w);                                                    \
        _Pragma("unroll")                                                      \
        for (int q = 0; q < 8; q++) S2[q] = ffma2(CUR[q], wp, S2[q]);          \
        /* deep prefetch: k_{T+4} into CUR */                                  \
        {                                                                      \
            int tk = ((T) + 4 < LL) ? (T) + 4 : LL - 1;                        \
            const float* kp = xb + (size_t)tk * DD;                            \
            _Pragma("unroll")                                                  \
            for (int q = 0; q < 8; q++)                                        \
                CUR[q] = *reinterpret_cast<const u64*>(kp + 64 * q);           \
        }                                                                      \
        {                                                                      \
            int tv = ((T) + 2 < LL) ? (T) + 2 : LL - 1;                        \
            VBUF = vb[(size_t)tv * DD];                                        \
            KKB  = kb[tv];                                                     \
            AJB  = ab[((T) + 1 < LL) ? (T) + 1 : LL - 1];                      \
        }                                                                      \
        rp = pl; wprev = w;                                                    \
        if (((T) & 63) == 63) {                                                \
            _Pragma("unroll")                                                  \
            for (int i = 0; i < 8; i++) S2[i] = fmul2(S2[i], lam64p);          \
            p = lam; pinv = invlam; sfix = lam64;                              \
        } else {                                                               \
            p *= lam; pinv *= invlam; sfix = 1.0f;                             \
        }                                                                      \
    } while (0)

    #pragma unroll 1
    for (int t = 0; t < LL; t += 4) {
        BODY(t,     K0, K1, vbuf0, kkbuf0, kadjbuf0);
        BODY(t + 1, K1, K2, vbuf1, kkbuf1, kadjbuf1);
        BODY(t + 2, K2, K3, vbuf0, kkbuf0, kadjbuf0);
        BODY(t + 3, K3, K0, vbuf1, kkbuf1, kadjbuf1);
    }
#undef BODY
}

// ============================================================
// 4) LayerNorm
// ============================================================
__global__ void ln_kernel(const float* __restrict__ gamma,
                          const float* __restrict__ lbeta,
                          float* __restrict__ out) {
    int row = blockIdx.x;
    int t = threadIdx.x;
    const float4* sp = reinterpret_cast<const float4*>(g_stat + (size_t)row * DD);
    const float4* op = reinterpret_cast<const float4*>(g_odyn + (size_t)row * DD);
    float4 sv = sp[t], ov = op[t];
    float4 y;
    y.x = sv.x + ov.x; y.y = sv.y + ov.y; y.z = sv.z + ov.z; y.w = sv.w + ov.w;

    float sum = y.x + y.y + y.z + y.w;
    float sq  = y.x*y.x + y.y*y.y + y.z*y.z + y.w*y.w;

    __shared__ float r1[4], r2[4];
    #pragma unroll
    for (int o = 16; o > 0; o >>= 1) {
        sum += __shfl_xor_sync(0xffffffffu, sum, o);
        sq  += __shfl_xor_sync(0xffffffffu, sq, o);
    }
    if ((t & 31) == 0) { r1[t >> 5] = sum; r2[t >> 5] = sq; }
    __syncthreads();
    __shared__ float smu, srs;
    if (t == 0) {
        float ts = r1[0] + r1[1] + r1[2] + r1[3];
        float tq = r2[0] + r2[1] + r2[2] + r2[3];
        float mu = ts * (1.0f / DD);
        float var = tq * (1.0f / DD) - mu * mu;
        smu = mu;
        srs = rsqrtf(var + 1e-5f);
    }
    __syncthreads();
    float mu = smu, rs = srs;

    const float4* gp = reinterpret_cast<const float4*>(gamma);
    const float4* bp = reinterpret_cast<const float4*>(lbeta);
    float4 gv = gp[t], bv = bp[t];
    float4 r;
    r.x = (y.x - mu) * rs * gv.x + bv.x;
    r.y = (y.y - mu) * rs * gv.y + bv.y;
    r.z = (y.z - mu) * rs * gv.z + bv.z;
    r.w = (y.w - mu) * rs * gv.w + bv.w;
    reinterpret_cast<float4*>(out + (size_t)row * DD)[t] = r;
}

// ============================================================
extern "C" void kernel_launch(void* const* d_in, const int* in_sizes, int n_in,
                              void* d_out, int out_size) {
    const float* x     = (const float*)d_in[0];
    const float* W     = (const float*)d_in[1];
    const float* eta   = (const float*)d_in[2];
    const float* laml  = (const float*)d_in[3];
    const float* gamma = (const float*)d_in[4];
    const float* lbeta = (const float*)d_in[5];
    float* out = (float*)d_out;

    // launch order keeps scan_kernel at index 3 (the launch ncu profiles)
    prep_kernel<<<NROW, 128>>>(x);
    kadj_kernel<<<NROW, 128>>>();
    gemm_kernel<<<dim3(DD / BN, NROW / BM), 256>>>(W);
    scan_kernel<<<128, 512>>>(eta, laml);
    ln_kernel<<<NROW, 128>>>(gamma, lbeta, out);
}